// round 1
// baseline (speedup 1.0000x reference)
#include <cuda_runtime.h>

#define N_NODES 50000
#define E_EDGES 1600000
#define IN_DIM  128
#define OUT_DIM 128   // H*D = 8*16
#define H_HEADS 8

// ---------------- scratch (static device globals: allowed) ----------------
__device__ __align__(16) float g_Q[N_NODES * OUT_DIM];
__device__ __align__(16) float g_K[N_NODES * OUT_DIM];
__device__ __align__(16) float g_V[N_NODES * OUT_DIM];
__device__ __align__(16) float g_z[N_NODES * H_HEADS];

// ---------------- zero accumulators ----------------
__global__ void zero_kernel(float* __restrict__ out) {
    int idx = blockIdx.x * blockDim.x + threadIdx.x;
    const int tot4 = (N_NODES * OUT_DIM) / 4;   // 1.6M float4
    if (idx < tot4)
        reinterpret_cast<float4*>(out)[idx] = make_float4(0.f, 0.f, 0.f, 0.f);
    const int totz4 = (N_NODES * H_HEADS) / 4;  // 100K float4
    if (idx < totz4)
        reinterpret_cast<float4*>(g_z)[idx] = make_float4(0.f, 0.f, 0.f, 0.f);
}

// ---------------- fused QKV projection: C = h @ W + b ----------------
// BM=128, BN=128(=OUT_DIM), BK=32. 256 threads, 8x8 microtile per thread.
// blockIdx.y selects {Q,K,V}.
#define BM 128
#define BK 32
#define AS_STRIDE 133   // conflict-free transposed-A stores (scalar reads are broadcast)

__global__ __launch_bounds__(256) void qkv_gemm(
    const float* __restrict__ hin,
    const float* __restrict__ WQ, const float* __restrict__ WK, const float* __restrict__ WV,
    const float* __restrict__ bQ, const float* __restrict__ bK, const float* __restrict__ bV)
{
    __shared__ float As[BK * AS_STRIDE];     // As[k][r]  (transposed)
    __shared__ float Bs[BK * OUT_DIM];       // Bs[k][c]

    const float* W;
    const float* bias;
    float* out;
    if (blockIdx.y == 0)      { W = WQ; bias = bQ; out = g_Q; }
    else if (blockIdx.y == 1) { W = WK; bias = bK; out = g_K; }
    else                      { W = WV; bias = bV; out = g_V; }

    const int t    = threadIdx.x;        // 0..255
    const int row0 = blockIdx.x * BM;
    const int ty   = t >> 4;             // 0..15
    const int tx   = t & 15;             // 0..15

    float acc[8][8];
#pragma unroll
    for (int i = 0; i < 8; i++)
#pragma unroll
        for (int j = 0; j < 8; j++) acc[i][j] = 0.f;

    for (int kt = 0; kt < IN_DIM; kt += BK) {
        // load A tile (128 rows x 32 cols), transpose into As[k][r]
#pragma unroll
        for (int i = 0; i < 4; i++) {
            int idx = t + i * 256;       // 0..1023 float4 slots
            int r   = idx >> 3;          // 0..127
            int c4  = idx & 7;           // 0..7
            int row = row0 + r;
            float4 v = make_float4(0.f, 0.f, 0.f, 0.f);
            if (row < N_NODES)
                v = *reinterpret_cast<const float4*>(&hin[(size_t)row * IN_DIM + kt + c4 * 4]);
            int k = c4 * 4;
            As[(k + 0) * AS_STRIDE + r] = v.x;
            As[(k + 1) * AS_STRIDE + r] = v.y;
            As[(k + 2) * AS_STRIDE + r] = v.z;
            As[(k + 3) * AS_STRIDE + r] = v.w;
        }
        // load B tile (32 rows x 128 cols)
#pragma unroll
        for (int i = 0; i < 4; i++) {
            int idx = t + i * 256;       // 0..1023 float4 slots
            int k   = idx >> 5;          // 0..31
            int c4  = idx & 31;          // 0..31
            *reinterpret_cast<float4*>(&Bs[k * OUT_DIM + c4 * 4]) =
                *reinterpret_cast<const float4*>(&W[(size_t)(kt + k) * OUT_DIM + c4 * 4]);
        }
        __syncthreads();

#pragma unroll
        for (int k = 0; k < BK; k++) {
            float a[8];
#pragma unroll
            for (int i = 0; i < 8; i++) a[i] = As[k * AS_STRIDE + ty * 8 + i];
            float4 b0 = *reinterpret_cast<const float4*>(&Bs[k * OUT_DIM + tx * 8]);
            float4 b1 = *reinterpret_cast<const float4*>(&Bs[k * OUT_DIM + tx * 8 + 4]);
            float b[8] = {b0.x, b0.y, b0.z, b0.w, b1.x, b1.y, b1.z, b1.w};
#pragma unroll
            for (int i = 0; i < 8; i++)
#pragma unroll
                for (int j = 0; j < 8; j++) acc[i][j] = fmaf(a[i], b[j], acc[i][j]);
        }
        __syncthreads();
    }

    // epilogue: + bias, write out
    float bb[8];
#pragma unroll
    for (int j = 0; j < 8; j++) bb[j] = __ldg(&bias[tx * 8 + j]);
#pragma unroll
    for (int i = 0; i < 8; i++) {
        int row = row0 + ty * 8 + i;
        if (row < N_NODES) {
            float4 o0 = make_float4(acc[i][0] + bb[0], acc[i][1] + bb[1],
                                    acc[i][2] + bb[2], acc[i][3] + bb[3]);
            float4 o1 = make_float4(acc[i][4] + bb[4], acc[i][5] + bb[5],
                                    acc[i][6] + bb[6], acc[i][7] + bb[7]);
            *reinterpret_cast<float4*>(&out[(size_t)row * OUT_DIM + tx * 8])     = o0;
            *reinterpret_cast<float4*>(&out[(size_t)row * OUT_DIM + tx * 8 + 4]) = o1;
        }
    }
}

// ---------------- edge kernel: warp per edge ----------------
// lane l handles dims [4l, 4l+4); head = l>>2 (4 lanes per head, D=16).
__global__ __launch_bounds__(256) void edge_kernel(
    const int* __restrict__ src, const int* __restrict__ dst,
    float* __restrict__ out)
{
    const int warp = (blockIdx.x * blockDim.x + threadIdx.x) >> 5;  // < E exactly
    const int lane = threadIdx.x & 31;

    const int s = src[warp];
    const int d = dst[warp];

    float4 kv = *reinterpret_cast<const float4*>(&g_K[(size_t)s * OUT_DIM + lane * 4]);
    float4 qv = *reinterpret_cast<const float4*>(&g_Q[(size_t)d * OUT_DIM + lane * 4]);

    float p = kv.x * qv.x + kv.y * qv.y + kv.z * qv.z + kv.w * qv.w;
    p += __shfl_xor_sync(0xFFFFFFFFu, p, 1);
    p += __shfl_xor_sync(0xFFFFFFFFu, p, 2);   // now each lane holds its head's dot

    // scale = sqrt(D) = 4
    float sc = __expf(fminf(fmaxf(p * 0.25f, -5.f), 5.f));

    float4 vv = *reinterpret_cast<const float4*>(&g_V[(size_t)s * OUT_DIM + lane * 4]);
    float* o = &out[(size_t)d * OUT_DIM + lane * 4];
    atomicAdd(o + 0, sc * vv.x);
    atomicAdd(o + 1, sc * vv.y);
    atomicAdd(o + 2, sc * vv.z);
    atomicAdd(o + 3, sc * vv.w);

    if ((lane & 3) == 0)
        atomicAdd(&g_z[(size_t)d * H_HEADS + (lane >> 2)], sc);
}

// ---------------- normalize in-place ----------------
__global__ void norm_kernel(float* __restrict__ out) {
    int idx4 = blockIdx.x * blockDim.x + threadIdx.x;
    const int tot4 = (N_NODES * OUT_DIM) / 4;
    if (idx4 < tot4) {
        float inv = 1.0f / g_z[idx4 >> 2];   // (idx4*4)>>4 == idx4>>2 -> [n*8+h]
        float4 v = reinterpret_cast<float4*>(out)[idx4];
        v.x *= inv; v.y *= inv; v.z *= inv; v.w *= inv;
        reinterpret_cast<float4*>(out)[idx4] = v;
    }
}

// ---------------- launch ----------------
extern "C" void kernel_launch(void* const* d_in, const int* in_sizes, int n_in,
                              void* d_out, int out_size)
{
    const float* h   = (const float*)d_in[0];
    const int*   src = (const int*)  d_in[1];
    const int*   dst = (const int*)  d_in[2];
    const float* WQ  = (const float*)d_in[3];
    const float* WK  = (const float*)d_in[4];
    const float* WV  = (const float*)d_in[5];
    const float* bQ  = (const float*)d_in[6];
    const float* bK  = (const float*)d_in[7];
    const float* bV  = (const float*)d_in[8];
    float* out = (float*)d_out;

    (void)in_sizes; (void)n_in; (void)out_size;

    // 1) zero wV(=out) and z
    zero_kernel<<<((N_NODES * OUT_DIM) / 4 + 255) / 256, 256>>>(out);

    // 2) fused QKV projection
    dim3 ggrid((N_NODES + BM - 1) / BM, 3);
    qkv_gemm<<<ggrid, 256>>>(h, WQ, WK, WV, bQ, bK, bV);

    // 3) edge score + scatter (warp per edge; E divisible by 8 warps/block)
    edge_kernel<<<E_EDGES / 8, 256>>>(src, dst, out);

    // 4) normalize
    norm_kernel<<<((N_NODES * OUT_DIM) / 4 + 255) / 256, 256>>>(out);
}

// round 4
// speedup vs baseline: 1.8894x; 1.8894x over previous
#include <cuda_runtime.h>

#define N_NODES 50000
#define E_EDGES 1600000
#define IN_DIM  128
#define OUT_DIM 128   // H*D = 8*16
#define H_HEADS 8

// ---------------- scratch (static device globals: allowed) ----------------
__device__ __align__(16) float g_Q[N_NODES * OUT_DIM];
__device__ __align__(16) float g_K[N_NODES * OUT_DIM];
__device__ __align__(16) float g_V[N_NODES * OUT_DIM];
__device__ int g_cnt[N_NODES];
__device__ int g_rowptr[N_NODES + 1];
__device__ int g_cursor[N_NODES];
__device__ int g_esrc[E_EDGES];

// ---------------- CSR build ----------------
__global__ void zero_cnt_kernel() {
    int i = blockIdx.x * blockDim.x + threadIdx.x;
    if (i < N_NODES) g_cnt[i] = 0;
}

__global__ void hist_kernel(const int* __restrict__ dst) {
    int e = blockIdx.x * blockDim.x + threadIdx.x;
    if (e < E_EDGES) atomicAdd(&g_cnt[dst[e]], 1);
}

// single-block scan: 1024 threads, each owns a chunk of 49 nodes
__global__ __launch_bounds__(1024) void scan_kernel() {
    __shared__ int sums[1024];
    const int CH = (N_NODES + 1023) / 1024;   // 49
    const int t = threadIdx.x;
    const int base = t * CH;
    int s = 0;
    for (int i = 0; i < CH; i++) {
        int idx = base + i;
        if (idx < N_NODES) s += g_cnt[idx];
    }
    sums[t] = s;
    __syncthreads();
    // Hillis-Steele inclusive scan
    for (int off = 1; off < 1024; off <<= 1) {
        int v = (t >= off) ? sums[t - off] : 0;
        __syncthreads();
        sums[t] += v;
        __syncthreads();
    }
    int run = sums[t] - s;   // exclusive prefix for this chunk
    for (int i = 0; i < CH; i++) {
        int idx = base + i;
        if (idx < N_NODES) {
            g_rowptr[idx] = run;
            g_cursor[idx] = run;
            run += g_cnt[idx];
        }
    }
    if (t == 0) g_rowptr[N_NODES] = E_EDGES;
}

__global__ void scatter_kernel(const int* __restrict__ src, const int* __restrict__ dst) {
    int e = blockIdx.x * blockDim.x + threadIdx.x;
    if (e < E_EDGES) {
        int d = dst[e];
        int pos = atomicAdd(&g_cursor[d], 1);
        g_esrc[pos] = src[e];
    }
}

// ---------------- fused QKV projection: C = h @ W + b ----------------
#define BM 128
#define BK 32
#define AS_STRIDE 133

__global__ __launch_bounds__(256) void qkv_gemm(
    const float* __restrict__ hin,
    const float* __restrict__ WQ, const float* __restrict__ WK, const float* __restrict__ WV,
    const float* __restrict__ bQ, const float* __restrict__ bK, const float* __restrict__ bV)
{
    __shared__ float As[BK * AS_STRIDE];     // As[k][r]
    __shared__ float Bs[BK * OUT_DIM];       // Bs[k][c]

    const float* W;
    const float* bias;
    float* out;
    if (blockIdx.y == 0)      { W = WQ; bias = bQ; out = g_Q; }
    else if (blockIdx.y == 1) { W = WK; bias = bK; out = g_K; }
    else                      { W = WV; bias = bV; out = g_V; }

    const int t    = threadIdx.x;
    const int row0 = blockIdx.x * BM;
    const int ty   = t >> 4;
    const int tx   = t & 15;

    float acc[8][8];
#pragma unroll
    for (int i = 0; i < 8; i++)
#pragma unroll
        for (int j = 0; j < 8; j++) acc[i][j] = 0.f;

    for (int kt = 0; kt < IN_DIM; kt += BK) {
#pragma unroll
        for (int i = 0; i < 4; i++) {
            int idx = t + i * 256;
            int r   = idx >> 3;
            int c4  = idx & 7;
            int row = row0 + r;
            float4 v = make_float4(0.f, 0.f, 0.f, 0.f);
            if (row < N_NODES)
                v = *reinterpret_cast<const float4*>(&hin[(size_t)row * IN_DIM + kt + c4 * 4]);
            int k = c4 * 4;
            As[(k + 0) * AS_STRIDE + r] = v.x;
            As[(k + 1) * AS_STRIDE + r] = v.y;
            As[(k + 2) * AS_STRIDE + r] = v.z;
            As[(k + 3) * AS_STRIDE + r] = v.w;
        }
#pragma unroll
        for (int i = 0; i < 4; i++) {
            int idx = t + i * 256;
            int k   = idx >> 5;
            int c4  = idx & 31;
            *reinterpret_cast<float4*>(&Bs[k * OUT_DIM + c4 * 4]) =
                *reinterpret_cast<const float4*>(&W[(size_t)(kt + k) * OUT_DIM + c4 * 4]);
        }
        __syncthreads();

#pragma unroll
        for (int k = 0; k < BK; k++) {
            float a[8];
#pragma unroll
            for (int i = 0; i < 8; i++) a[i] = As[k * AS_STRIDE + ty * 8 + i];
            float4 b0 = *reinterpret_cast<const float4*>(&Bs[k * OUT_DIM + tx * 8]);
            float4 b1 = *reinterpret_cast<const float4*>(&Bs[k * OUT_DIM + tx * 8 + 4]);
            float b[8] = {b0.x, b0.y, b0.z, b0.w, b1.x, b1.y, b1.z, b1.w};
#pragma unroll
            for (int i = 0; i < 8; i++)
#pragma unroll
                for (int j = 0; j < 8; j++) acc[i][j] = fmaf(a[i], b[j], acc[i][j]);
        }
        __syncthreads();
    }

    float bb[8];
#pragma unroll
    for (int j = 0; j < 8; j++) bb[j] = __ldg(&bias[tx * 8 + j]);
#pragma unroll
    for (int i = 0; i < 8; i++) {
        int row = row0 + ty * 8 + i;
        if (row < N_NODES) {
            float4 o0 = make_float4(acc[i][0] + bb[0], acc[i][1] + bb[1],
                                    acc[i][2] + bb[2], acc[i][3] + bb[3]);
            float4 o1 = make_float4(acc[i][4] + bb[4], acc[i][5] + bb[5],
                                    acc[i][6] + bb[6], acc[i][7] + bb[7]);
            *reinterpret_cast<float4*>(&out[(size_t)row * OUT_DIM + tx * 8])     = o0;
            *reinterpret_cast<float4*>(&out[(size_t)row * OUT_DIM + tx * 8 + 4]) = o1;
        }
    }
}

// ---------------- gather kernel: warp per dst node, atomic-free ----------------
// lane l handles dims [4l,4l+4); head = l>>2. Normalization fused.
__device__ __forceinline__ float edge_score(const float4& kv, const float4& qv) {
    float p = kv.x * qv.x + kv.y * qv.y + kv.z * qv.z + kv.w * qv.w;
    p += __shfl_xor_sync(0xFFFFFFFFu, p, 1);
    p += __shfl_xor_sync(0xFFFFFFFFu, p, 2);
    return __expf(fminf(fmaxf(p * 0.25f, -5.f), 5.f));
}

__global__ __launch_bounds__(256) void gather_kernel(float* __restrict__ out) {
    const int node = (blockIdx.x * blockDim.x + threadIdx.x) >> 5;
    if (node >= N_NODES) return;
    const int lane = threadIdx.x & 31;

    const float4 qv = *reinterpret_cast<const float4*>(&g_Q[(size_t)node * OUT_DIM + lane * 4]);
    const int beg = __ldg(&g_rowptr[node]);
    const int end = __ldg(&g_rowptr[node + 1]);

    float ax = 0.f, ay = 0.f, az = 0.f, aw = 0.f, z = 0.f;

    int i = beg;
    // 4-edge unrolled pipeline: front-batch 8 float4 gathers for MLP
    for (; i + 3 < end; i += 4) {
        int s0 = __ldg(&g_esrc[i]);
        int s1 = __ldg(&g_esrc[i + 1]);
        int s2 = __ldg(&g_esrc[i + 2]);
        int s3 = __ldg(&g_esrc[i + 3]);
        const float4* k0p = reinterpret_cast<const float4*>(&g_K[(size_t)s0 * OUT_DIM + lane * 4]);
        const float4* k1p = reinterpret_cast<const float4*>(&g_K[(size_t)s1 * OUT_DIM + lane * 4]);
        const float4* k2p = reinterpret_cast<const float4*>(&g_K[(size_t)s2 * OUT_DIM + lane * 4]);
        const float4* k3p = reinterpret_cast<const float4*>(&g_K[(size_t)s3 * OUT_DIM + lane * 4]);
        const float4* v0p = reinterpret_cast<const float4*>(&g_V[(size_t)s0 * OUT_DIM + lane * 4]);
        const float4* v1p = reinterpret_cast<const float4*>(&g_V[(size_t)s1 * OUT_DIM + lane * 4]);
        const float4* v2p = reinterpret_cast<const float4*>(&g_V[(size_t)s2 * OUT_DIM + lane * 4]);
        const float4* v3p = reinterpret_cast<const float4*>(&g_V[(size_t)s3 * OUT_DIM + lane * 4]);
        float4 k0 = *k0p, k1 = *k1p, k2 = *k2p, k3 = *k3p;
        float4 v0 = *v0p, v1 = *v1p, v2 = *v2p, v3 = *v3p;
        float sc0 = edge_score(k0, qv);
        float sc1 = edge_score(k1, qv);
        float sc2 = edge_score(k2, qv);
        float sc3 = edge_score(k3, qv);
        ax = fmaf(sc0, v0.x, ax); ay = fmaf(sc0, v0.y, ay);
        az = fmaf(sc0, v0.z, az); aw = fmaf(sc0, v0.w, aw);
        ax = fmaf(sc1, v1.x, ax); ay = fmaf(sc1, v1.y, ay);
        az = fmaf(sc1, v1.z, az); aw = fmaf(sc1, v1.w, aw);
        ax = fmaf(sc2, v2.x, ax); ay = fmaf(sc2, v2.y, ay);
        az = fmaf(sc2, v2.z, az); aw = fmaf(sc2, v2.w, aw);
        ax = fmaf(sc3, v3.x, ax); ay = fmaf(sc3, v3.y, ay);
        az = fmaf(sc3, v3.z, az); aw = fmaf(sc3, v3.w, aw);
        z += (sc0 + sc1) + (sc2 + sc3);
    }
    for (; i < end; i++) {
        int s0 = __ldg(&g_esrc[i]);
        float4 k0 = *reinterpret_cast<const float4*>(&g_K[(size_t)s0 * OUT_DIM + lane * 4]);
        float4 v0 = *reinterpret_cast<const float4*>(&g_V[(size_t)s0 * OUT_DIM + lane * 4]);
        float sc0 = edge_score(k0, qv);
        ax = fmaf(sc0, v0.x, ax); ay = fmaf(sc0, v0.y, ay);
        az = fmaf(sc0, v0.z, az); aw = fmaf(sc0, v0.w, aw);
        z += sc0;
    }

    const float inv = 1.0f / z;   // z identical across the 4 lanes of each head
    float4 o = make_float4(ax * inv, ay * inv, az * inv, aw * inv);
    *reinterpret_cast<float4*>(&out[(size_t)node * OUT_DIM + lane * 4]) = o;
}

// ---------------- launch ----------------
extern "C" void kernel_launch(void* const* d_in, const int* in_sizes, int n_in,
                              void* d_out, int out_size)
{
    const float* h   = (const float*)d_in[0];
    const int*   src = (const int*)  d_in[1];
    const int*   dst = (const int*)  d_in[2];
    const float* WQ  = (const float*)d_in[3];
    const float* WK  = (const float*)d_in[4];
    const float* WV  = (const float*)d_in[5];
    const float* bQ  = (const float*)d_in[6];
    const float* bK  = (const float*)d_in[7];
    const float* bV  = (const float*)d_in[8];
    float* out = (float*)d_out;

    (void)in_sizes; (void)n_in; (void)out_size;

    // CSR build (by destination)
    zero_cnt_kernel<<<(N_NODES + 255) / 256, 256>>>();
    hist_kernel<<<(E_EDGES + 255) / 256, 256>>>(dst);
    scan_kernel<<<1, 1024>>>();
    scatter_kernel<<<(E_EDGES + 255) / 256, 256>>>(src, dst);

    // QKV projection
    dim3 ggrid((N_NODES + BM - 1) / BM, 3);
    qkv_gemm<<<ggrid, 256>>>(h, WQ, WK, WV, bQ, bK, bV);

    // warp-per-node gather + fused normalize (atomic-free)
    gather_kernel<<<(N_NODES * 32 + 255) / 256, 256>>>(out);
}

// round 5
// speedup vs baseline: 2.6917x; 1.4247x over previous
#include <cuda_runtime.h>
#include <cuda_fp16.h>

#define N_NODES 50000
#define E_EDGES 1600000
#define IN_DIM  128
#define OUT_DIM 128   // H*D = 8*16
#define H_HEADS 8

// ---------------- scratch (static device globals: allowed) ----------------
__device__ __align__(16) __half g_Qh[N_NODES * OUT_DIM];
__device__ __align__(16) __half g_Kh[N_NODES * OUT_DIM];
__device__ __align__(16) __half g_Vh[N_NODES * OUT_DIM];
__device__ int g_cnt[N_NODES];
__device__ int g_rowptr[N_NODES + 1];
__device__ int g_cursor[N_NODES];
__device__ int g_esrc[E_EDGES];

// ---------------- CSR build ----------------
__global__ void zero_cnt_kernel() {
    int i = blockIdx.x * blockDim.x + threadIdx.x;
    if (i < N_NODES) g_cnt[i] = 0;
}

__global__ void hist_kernel(const int* __restrict__ dst) {
    int e = blockIdx.x * blockDim.x + threadIdx.x;
    if (e < E_EDGES) atomicAdd(&g_cnt[dst[e]], 1);
}

__global__ __launch_bounds__(1024) void scan_kernel() {
    __shared__ int sums[1024];
    const int CH = (N_NODES + 1023) / 1024;   // 49
    const int t = threadIdx.x;
    const int base = t * CH;
    int s = 0;
    for (int i = 0; i < CH; i++) {
        int idx = base + i;
        if (idx < N_NODES) s += g_cnt[idx];
    }
    sums[t] = s;
    __syncthreads();
    for (int off = 1; off < 1024; off <<= 1) {
        int v = (t >= off) ? sums[t - off] : 0;
        __syncthreads();
        sums[t] += v;
        __syncthreads();
    }
    int run = sums[t] - s;
    for (int i = 0; i < CH; i++) {
        int idx = base + i;
        if (idx < N_NODES) {
            g_rowptr[idx] = run;
            g_cursor[idx] = run;
            run += g_cnt[idx];
        }
    }
    if (t == 0) g_rowptr[N_NODES] = E_EDGES;
}

__global__ void scatter_kernel(const int* __restrict__ src, const int* __restrict__ dst) {
    int e = blockIdx.x * blockDim.x + threadIdx.x;
    if (e < E_EDGES) {
        int d = dst[e];
        int pos = atomicAdd(&g_cursor[d], 1);
        g_esrc[pos] = src[e];
    }
}

// ---------------- fp16 tensor-core fused QKV GEMM ----------------
// Tile: 128 rows x 128 cols, K=128 processed in two 64-wide halves.
// 256 threads = 8 warps arranged 4(m) x 2(n); warp tile = 32m x 64n.
#define GK 64                 // k-half width
#define AS_LD 72              // (GK+8) halfs per A row
#define WS_LD 136             // (128+8) halfs per W row

__device__ __forceinline__ void ldsm_x4(unsigned& r0, unsigned& r1, unsigned& r2, unsigned& r3,
                                        const __half* p) {
    unsigned addr = (unsigned)__cvta_generic_to_shared(p);
    asm volatile("ldmatrix.sync.aligned.m8n8.x4.shared.b16 {%0,%1,%2,%3}, [%4];"
                 : "=r"(r0), "=r"(r1), "=r"(r2), "=r"(r3) : "r"(addr));
}
__device__ __forceinline__ void ldsm_x4_t(unsigned& r0, unsigned& r1, unsigned& r2, unsigned& r3,
                                          const __half* p) {
    unsigned addr = (unsigned)__cvta_generic_to_shared(p);
    asm volatile("ldmatrix.sync.aligned.m8n8.x4.trans.shared.b16 {%0,%1,%2,%3}, [%4];"
                 : "=r"(r0), "=r"(r1), "=r"(r2), "=r"(r3) : "r"(addr));
}
__device__ __forceinline__ void mma16816(float* c, const unsigned* a, const unsigned* b) {
    asm volatile(
        "mma.sync.aligned.m16n8k16.row.col.f32.f16.f16.f32 "
        "{%0,%1,%2,%3}, {%4,%5,%6,%7}, {%8,%9}, {%0,%1,%2,%3};"
        : "+f"(c[0]), "+f"(c[1]), "+f"(c[2]), "+f"(c[3])
        : "r"(a[0]), "r"(a[1]), "r"(a[2]), "r"(a[3]), "r"(b[0]), "r"(b[1]));
}

__global__ __launch_bounds__(256) void qkv_gemm_f16(
    const float* __restrict__ hin,
    const float* __restrict__ WQ, const float* __restrict__ WK, const float* __restrict__ WV,
    const float* __restrict__ bQ, const float* __restrict__ bK, const float* __restrict__ bV)
{
    __shared__ __half As[128 * AS_LD];   // [row][k]  (k-half)
    __shared__ __half Ws[GK * WS_LD];    // [k][n]    (k-half)

    const float* W;
    const float* bias;
    __half* out;
    if (blockIdx.y == 0)      { W = WQ; bias = bQ; out = g_Qh; }
    else if (blockIdx.y == 1) { W = WK; bias = bK; out = g_Kh; }
    else                      { W = WV; bias = bV; out = g_Vh; }

    const int t      = threadIdx.x;
    const int lane   = t & 31;
    const int wid    = t >> 5;
    const int warp_m = wid >> 1;        // 0..3 -> rows [warp_m*32, +32)
    const int warp_n = wid & 1;         // 0..1 -> cols [warp_n*64, +64)
    const int row0   = blockIdx.x * 128;

    float acc[2][8][4];
#pragma unroll
    for (int i = 0; i < 2; i++)
#pragma unroll
        for (int j = 0; j < 8; j++)
#pragma unroll
            for (int c = 0; c < 4; c++) acc[i][j][c] = 0.f;

    for (int kt = 0; kt < IN_DIM; kt += GK) {
        // A tile: 128 rows x 64 cols fp32 -> fp16 smem. 2048 float4, 8/thread.
#pragma unroll
        for (int i = 0; i < 8; i++) {
            int idx = t + i * 256;
            int r   = idx >> 4;        // 0..127
            int c4  = idx & 15;        // 0..15
            int row = row0 + r;
            float4 v = make_float4(0.f, 0.f, 0.f, 0.f);
            if (row < N_NODES)
                v = *reinterpret_cast<const float4*>(&hin[(size_t)row * IN_DIM + kt + c4 * 4]);
            __half2 h0 = __floats2half2_rn(v.x, v.y);
            __half2 h1 = __floats2half2_rn(v.z, v.w);
            *reinterpret_cast<__half2*>(&As[r * AS_LD + c4 * 4])     = h0;
            *reinterpret_cast<__half2*>(&As[r * AS_LD + c4 * 4 + 2]) = h1;
        }
        // W tile: 64 k-rows x 128 cols fp32 -> fp16 smem. 2048 float4, 8/thread.
#pragma unroll
        for (int i = 0; i < 8; i++) {
            int idx = t + i * 256;
            int k   = idx >> 5;        // 0..63
            int c4  = idx & 31;        // 0..31
            float4 v = *reinterpret_cast<const float4*>(&W[(size_t)(kt + k) * OUT_DIM + c4 * 4]);
            __half2 h0 = __floats2half2_rn(v.x, v.y);
            __half2 h1 = __floats2half2_rn(v.z, v.w);
            *reinterpret_cast<__half2*>(&Ws[k * WS_LD + c4 * 4])     = h0;
            *reinterpret_cast<__half2*>(&Ws[k * WS_LD + c4 * 4 + 2]) = h1;
        }
        __syncthreads();

#pragma unroll
        for (int kk = 0; kk < GK; kk += 16) {
            unsigned a[2][4];
#pragma unroll
            for (int i = 0; i < 2; i++) {
                int r = warp_m * 32 + i * 16 + (lane & 15);
                int c = kk + 8 * (lane >> 4);
                ldsm_x4(a[i][0], a[i][1], a[i][2], a[i][3], &As[r * AS_LD + c]);
            }
            unsigned b[4][4];
#pragma unroll
            for (int j = 0; j < 4; j++) {
                int kr = kk + (lane & 15);
                int c  = warp_n * 64 + j * 16 + 8 * (lane >> 4);
                ldsm_x4_t(b[j][0], b[j][1], b[j][2], b[j][3], &Ws[kr * WS_LD + c]);
            }
#pragma unroll
            for (int i = 0; i < 2; i++)
#pragma unroll
                for (int j2 = 0; j2 < 8; j2++)
                    mma16816(acc[i][j2], a[i], &b[j2 >> 1][(j2 & 1) * 2]);
        }
        __syncthreads();
    }

    // epilogue: + bias, convert to fp16, store half2
#pragma unroll
    for (int i = 0; i < 2; i++) {
        int row_a = row0 + warp_m * 32 + i * 16 + (lane >> 2);
        int row_b = row_a + 8;
#pragma unroll
        for (int j2 = 0; j2 < 8; j2++) {
            int col = warp_n * 64 + j2 * 8 + (lane & 3) * 2;
            float b0 = __ldg(&bias[col]);
            float b1 = __ldg(&bias[col + 1]);
            if (row_a < N_NODES) {
                __half2 o = __floats2half2_rn(acc[i][j2][0] + b0, acc[i][j2][1] + b1);
                *reinterpret_cast<__half2*>(&out[(size_t)row_a * OUT_DIM + col]) = o;
            }
            if (row_b < N_NODES) {
                __half2 o = __floats2half2_rn(acc[i][j2][2] + b0, acc[i][j2][3] + b1);
                *reinterpret_cast<__half2*>(&out[(size_t)row_b * OUT_DIM + col]) = o;
            }
        }
    }
}

// ---------------- gather kernel: warp per dst node, fp16 K/V/Q ----------------
// lane l handles dims [4l,4l+4); head = l>>2. Normalization fused.
struct F4 { float x, y, z, w; };

__device__ __forceinline__ F4 ld_half4(const __half* p) {
    uint2 raw = *reinterpret_cast<const uint2*>(p);
    __half2 h0 = *reinterpret_cast<__half2*>(&raw.x);
    __half2 h1 = *reinterpret_cast<__half2*>(&raw.y);
    float2 f0 = __half22float2(h0);
    float2 f1 = __half22float2(h1);
    F4 r; r.x = f0.x; r.y = f0.y; r.z = f1.x; r.w = f1.y;
    return r;
}

__device__ __forceinline__ float edge_score(const F4& kv, const F4& qv) {
    float p = kv.x * qv.x + kv.y * qv.y + kv.z * qv.z + kv.w * qv.w;
    p += __shfl_xor_sync(0xFFFFFFFFu, p, 1);
    p += __shfl_xor_sync(0xFFFFFFFFu, p, 2);
    return __expf(fminf(fmaxf(p * 0.25f, -5.f), 5.f));
}

__global__ __launch_bounds__(256) void gather_kernel(float* __restrict__ out) {
    const int node = (blockIdx.x * blockDim.x + threadIdx.x) >> 5;
    if (node >= N_NODES) return;
    const int lane = threadIdx.x & 31;

    const F4 qv = ld_half4(&g_Qh[(size_t)node * OUT_DIM + lane * 4]);
    const int beg = __ldg(&g_rowptr[node]);
    const int end = __ldg(&g_rowptr[node + 1]);

    float ax = 0.f, ay = 0.f, az = 0.f, aw = 0.f, z = 0.f;

    int i = beg;
    for (; i + 3 < end; i += 4) {
        int s0 = __ldg(&g_esrc[i]);
        int s1 = __ldg(&g_esrc[i + 1]);
        int s2 = __ldg(&g_esrc[i + 2]);
        int s3 = __ldg(&g_esrc[i + 3]);
        F4 k0 = ld_half4(&g_Kh[(size_t)s0 * OUT_DIM + lane * 4]);
        F4 k1 = ld_half4(&g_Kh[(size_t)s1 * OUT_DIM + lane * 4]);
        F4 k2 = ld_half4(&g_Kh[(size_t)s2 * OUT_DIM + lane * 4]);
        F4 k3 = ld_half4(&g_Kh[(size_t)s3 * OUT_DIM + lane * 4]);
        F4 v0 = ld_half4(&g_Vh[(size_t)s0 * OUT_DIM + lane * 4]);
        F4 v1 = ld_half4(&g_Vh[(size_t)s1 * OUT_DIM + lane * 4]);
        F4 v2 = ld_half4(&g_Vh[(size_t)s2 * OUT_DIM + lane * 4]);
        F4 v3 = ld_half4(&g_Vh[(size_t)s3 * OUT_DIM + lane * 4]);
        float sc0 = edge_score(k0, qv);
        float sc1 = edge_score(k1, qv);
        float sc2 = edge_score(k2, qv);
        float sc3 = edge_score(k3, qv);
        ax = fmaf(sc0, v0.x, ax); ay = fmaf(sc0, v0.y, ay);
        az = fmaf(sc0, v0.z, az); aw = fmaf(sc0, v0.w, aw);
        ax = fmaf(sc1, v1.x, ax); ay = fmaf(sc1, v1.y, ay);
        az = fmaf(sc1, v1.z, az); aw = fmaf(sc1, v1.w, aw);
        ax = fmaf(sc2, v2.x, ax); ay = fmaf(sc2, v2.y, ay);
        az = fmaf(sc2, v2.z, az); aw = fmaf(sc2, v2.w, aw);
        ax = fmaf(sc3, v3.x, ax); ay = fmaf(sc3, v3.y, ay);
        az = fmaf(sc3, v3.z, az); aw = fmaf(sc3, v3.w, aw);
        z += (sc0 + sc1) + (sc2 + sc3);
    }
    for (; i < end; i++) {
        int s0 = __ldg(&g_esrc[i]);
        F4 k0 = ld_half4(&g_Kh[(size_t)s0 * OUT_DIM + lane * 4]);
        F4 v0 = ld_half4(&g_Vh[(size_t)s0 * OUT_DIM + lane * 4]);
        float sc0 = edge_score(k0, qv);
        ax = fmaf(sc0, v0.x, ax); ay = fmaf(sc0, v0.y, ay);
        az = fmaf(sc0, v0.z, az); aw = fmaf(sc0, v0.w, aw);
        z += sc0;
    }

    const float inv = 1.0f / z;
    float4 o = make_float4(ax * inv, ay * inv, az * inv, aw * inv);
    *reinterpret_cast<float4*>(&out[(size_t)node * OUT_DIM + lane * 4]) = o;
}

// ---------------- launch ----------------
extern "C" void kernel_launch(void* const* d_in, const int* in_sizes, int n_in,
                              void* d_out, int out_size)
{
    const float* h   = (const float*)d_in[0];
    const int*   src = (const int*)  d_in[1];
    const int*   dst = (const int*)  d_in[2];
    const float* WQ  = (const float*)d_in[3];
    const float* WK  = (const float*)d_in[4];
    const float* WV  = (const float*)d_in[5];
    const float* bQ  = (const float*)d_in[6];
    const float* bK  = (const float*)d_in[7];
    const float* bV  = (const float*)d_in[8];
    float* out = (float*)d_out;

    (void)in_sizes; (void)n_in; (void)out_size;

    // CSR build (by destination)
    zero_cnt_kernel<<<(N_NODES + 255) / 256, 256>>>();
    hist_kernel<<<(E_EDGES + 255) / 256, 256>>>(dst);
    scan_kernel<<<1, 1024>>>();
    scatter_kernel<<<(E_EDGES + 255) / 256, 256>>>(src, dst);

    // fp16 tensor-core QKV projection
    dim3 ggrid((N_NODES + 127) / 128, 3);
    qkv_gemm_f16<<<ggrid, 256>>>(h, WQ, WK, WV, bQ, bK, bV);

    // warp-per-node gather + fused normalize (atomic-free)
    gather_kernel<<<(N_NODES * 32 + 255) / 256, 256>>>(out);
}

// round 6
// speedup vs baseline: 2.7108x; 1.0071x over previous
#include <cuda_runtime.h>
#include <cuda_fp16.h>

#define N_NODES 50000
#define E_EDGES 1600000
#define IN_DIM  128
#define OUT_DIM 128   // H*D = 8*16
#define H_HEADS 8

// ---------------- scratch (static device globals: allowed) ----------------
__device__ __align__(16) __half g_Qh[N_NODES * OUT_DIM];
__device__ __align__(16) __half g_Kh[N_NODES * OUT_DIM];
__device__ __align__(16) __half g_Vh[N_NODES * OUT_DIM];
__device__ int g_cnt[N_NODES];
__device__ int g_rowptr[N_NODES + 1];
__device__ int g_cursor[N_NODES];
__device__ int g_esrc[E_EDGES];

// ---------------- CSR build ----------------
__global__ void zero_cnt_kernel() {
    int i = blockIdx.x * blockDim.x + threadIdx.x;
    if (i < N_NODES) g_cnt[i] = 0;
}

// 4 edges per thread: 4 outstanding REDG per thread (latency-bound -> 4x MLP)
__global__ void hist_kernel(const int* __restrict__ dst) {
    int i = blockIdx.x * blockDim.x + threadIdx.x;   // < E/4
    if (i < E_EDGES / 4) {
        int4 d = reinterpret_cast<const int4*>(dst)[i];
        atomicAdd(&g_cnt[d.x], 1);
        atomicAdd(&g_cnt[d.y], 1);
        atomicAdd(&g_cnt[d.z], 1);
        atomicAdd(&g_cnt[d.w], 1);
    }
}

__global__ __launch_bounds__(1024) void scan_kernel() {
    __shared__ int sums[1024];
    const int CH = (N_NODES + 1023) / 1024;   // 49
    const int t = threadIdx.x;
    const int base = t * CH;
    int s = 0;
    for (int i = 0; i < CH; i++) {
        int idx = base + i;
        if (idx < N_NODES) s += g_cnt[idx];
    }
    sums[t] = s;
    __syncthreads();
    for (int off = 1; off < 1024; off <<= 1) {
        int v = (t >= off) ? sums[t - off] : 0;
        __syncthreads();
        sums[t] += v;
        __syncthreads();
    }
    int run = sums[t] - s;
    for (int i = 0; i < CH; i++) {
        int idx = base + i;
        if (idx < N_NODES) {
            g_rowptr[idx] = run;
            g_cursor[idx] = run;
            run += g_cnt[idx];
        }
    }
    if (t == 0) g_rowptr[N_NODES] = E_EDGES;
}

// 4 edges per thread: 4 outstanding ATOMG per thread
__global__ void scatter_kernel(const int* __restrict__ src, const int* __restrict__ dst) {
    int i = blockIdx.x * blockDim.x + threadIdx.x;   // < E/4
    if (i < E_EDGES / 4) {
        int4 d = reinterpret_cast<const int4*>(dst)[i];
        int4 s = reinterpret_cast<const int4*>(src)[i];
        int p0 = atomicAdd(&g_cursor[d.x], 1);
        int p1 = atomicAdd(&g_cursor[d.y], 1);
        int p2 = atomicAdd(&g_cursor[d.z], 1);
        int p3 = atomicAdd(&g_cursor[d.w], 1);
        g_esrc[p0] = s.x;
        g_esrc[p1] = s.y;
        g_esrc[p2] = s.z;
        g_esrc[p3] = s.w;
    }
}

// ---------------- fp16 tensor-core fused QKV GEMM ----------------
#define GK 64                 // k-half width
#define AS_LD 72              // (GK+8) halfs per A row
#define WS_LD 136             // (128+8) halfs per W row

__device__ __forceinline__ void ldsm_x4(unsigned& r0, unsigned& r1, unsigned& r2, unsigned& r3,
                                        const __half* p) {
    unsigned addr = (unsigned)__cvta_generic_to_shared(p);
    asm volatile("ldmatrix.sync.aligned.m8n8.x4.shared.b16 {%0,%1,%2,%3}, [%4];"
                 : "=r"(r0), "=r"(r1), "=r"(r2), "=r"(r3) : "r"(addr));
}
__device__ __forceinline__ void ldsm_x4_t(unsigned& r0, unsigned& r1, unsigned& r2, unsigned& r3,
                                          const __half* p) {
    unsigned addr = (unsigned)__cvta_generic_to_shared(p);
    asm volatile("ldmatrix.sync.aligned.m8n8.x4.trans.shared.b16 {%0,%1,%2,%3}, [%4];"
                 : "=r"(r0), "=r"(r1), "=r"(r2), "=r"(r3) : "r"(addr));
}
__device__ __forceinline__ void mma16816(float* c, const unsigned* a, const unsigned* b) {
    asm volatile(
        "mma.sync.aligned.m16n8k16.row.col.f32.f16.f16.f32 "
        "{%0,%1,%2,%3}, {%4,%5,%6,%7}, {%8,%9}, {%0,%1,%2,%3};"
        : "+f"(c[0]), "+f"(c[1]), "+f"(c[2]), "+f"(c[3])
        : "r"(a[0]), "r"(a[1]), "r"(a[2]), "r"(a[3]), "r"(b[0]), "r"(b[1]));
}

__global__ __launch_bounds__(256) void qkv_gemm_f16(
    const float* __restrict__ hin,
    const float* __restrict__ WQ, const float* __restrict__ WK, const float* __restrict__ WV,
    const float* __restrict__ bQ, const float* __restrict__ bK, const float* __restrict__ bV)
{
    __shared__ __half As[128 * AS_LD];
    __shared__ __half Ws[GK * WS_LD];

    const float* W;
    const float* bias;
    __half* out;
    if (blockIdx.y == 0)      { W = WQ; bias = bQ; out = g_Qh; }
    else if (blockIdx.y == 1) { W = WK; bias = bK; out = g_Kh; }
    else                      { W = WV; bias = bV; out = g_Vh; }

    const int t      = threadIdx.x;
    const int lane   = t & 31;
    const int wid    = t >> 5;
    const int warp_m = wid >> 1;
    const int warp_n = wid & 1;
    const int row0   = blockIdx.x * 128;

    float acc[2][8][4];
#pragma unroll
    for (int i = 0; i < 2; i++)
#pragma unroll
        for (int j = 0; j < 8; j++)
#pragma unroll
            for (int c = 0; c < 4; c++) acc[i][j][c] = 0.f;

    for (int kt = 0; kt < IN_DIM; kt += GK) {
#pragma unroll
        for (int i = 0; i < 8; i++) {
            int idx = t + i * 256;
            int r   = idx >> 4;
            int c4  = idx & 15;
            int row = row0 + r;
            float4 v = make_float4(0.f, 0.f, 0.f, 0.f);
            if (row < N_NODES)
                v = *reinterpret_cast<const float4*>(&hin[(size_t)row * IN_DIM + kt + c4 * 4]);
            __half2 h0 = __floats2half2_rn(v.x, v.y);
            __half2 h1 = __floats2half2_rn(v.z, v.w);
            *reinterpret_cast<__half2*>(&As[r * AS_LD + c4 * 4])     = h0;
            *reinterpret_cast<__half2*>(&As[r * AS_LD + c4 * 4 + 2]) = h1;
        }
#pragma unroll
        for (int i = 0; i < 8; i++) {
            int idx = t + i * 256;
            int k   = idx >> 5;
            int c4  = idx & 31;
            float4 v = *reinterpret_cast<const float4*>(&W[(size_t)(kt + k) * OUT_DIM + c4 * 4]);
            __half2 h0 = __floats2half2_rn(v.x, v.y);
            __half2 h1 = __floats2half2_rn(v.z, v.w);
            *reinterpret_cast<__half2*>(&Ws[k * WS_LD + c4 * 4])     = h0;
            *reinterpret_cast<__half2*>(&Ws[k * WS_LD + c4 * 4 + 2]) = h1;
        }
        __syncthreads();

#pragma unroll
        for (int kk = 0; kk < GK; kk += 16) {
            unsigned a[2][4];
#pragma unroll
            for (int i = 0; i < 2; i++) {
                int r = warp_m * 32 + i * 16 + (lane & 15);
                int c = kk + 8 * (lane >> 4);
                ldsm_x4(a[i][0], a[i][1], a[i][2], a[i][3], &As[r * AS_LD + c]);
            }
            unsigned b[4][4];
#pragma unroll
            for (int j = 0; j < 4; j++) {
                int kr = kk + (lane & 15);
                int c  = warp_n * 64 + j * 16 + 8 * (lane >> 4);
                ldsm_x4_t(b[j][0], b[j][1], b[j][2], b[j][3], &Ws[kr * WS_LD + c]);
            }
#pragma unroll
            for (int i = 0; i < 2; i++)
#pragma unroll
                for (int j2 = 0; j2 < 8; j2++)
                    mma16816(acc[i][j2], a[i], &b[j2 >> 1][(j2 & 1) * 2]);
        }
        __syncthreads();
    }

#pragma unroll
    for (int i = 0; i < 2; i++) {
        int row_a = row0 + warp_m * 32 + i * 16 + (lane >> 2);
        int row_b = row_a + 8;
#pragma unroll
        for (int j2 = 0; j2 < 8; j2++) {
            int col = warp_n * 64 + j2 * 8 + (lane & 3) * 2;
            float b0 = __ldg(&bias[col]);
            float b1 = __ldg(&bias[col + 1]);
            if (row_a < N_NODES) {
                __half2 o = __floats2half2_rn(acc[i][j2][0] + b0, acc[i][j2][1] + b1);
                *reinterpret_cast<__half2*>(&out[(size_t)row_a * OUT_DIM + col]) = o;
            }
            if (row_b < N_NODES) {
                __half2 o = __floats2half2_rn(acc[i][j2][2] + b0, acc[i][j2][3] + b1);
                *reinterpret_cast<__half2*>(&out[(size_t)row_b * OUT_DIM + col]) = o;
            }
        }
    }
}

// ---------------- gather kernel: warp per dst node, fp16, 8-edge pipeline ----
struct F4 { float x, y, z, w; };

__device__ __forceinline__ F4 cvt_half4(uint2 raw) {
    __half2 h0 = *reinterpret_cast<__half2*>(&raw.x);
    __half2 h1 = *reinterpret_cast<__half2*>(&raw.y);
    float2 f0 = __half22float2(h0);
    float2 f1 = __half22float2(h1);
    F4 r; r.x = f0.x; r.y = f0.y; r.z = f1.x; r.w = f1.y;
    return r;
}

__device__ __forceinline__ float edge_score(const F4& kv, const F4& qv) {
    float p = kv.x * qv.x + kv.y * qv.y + kv.z * qv.z + kv.w * qv.w;
    p += __shfl_xor_sync(0xFFFFFFFFu, p, 1);
    p += __shfl_xor_sync(0xFFFFFFFFu, p, 2);
    return __expf(fminf(fmaxf(p * 0.25f, -5.f), 5.f));
}

__global__ __launch_bounds__(256) void gather_kernel(float* __restrict__ out) {
    const int node = (blockIdx.x * blockDim.x + threadIdx.x) >> 5;
    if (node >= N_NODES) return;
    const int lane = threadIdx.x & 31;

    const F4 qv = cvt_half4(*reinterpret_cast<const uint2*>(&g_Qh[(size_t)node * OUT_DIM + lane * 4]));
    const int beg = __ldg(&g_rowptr[node]);
    const int end = __ldg(&g_rowptr[node + 1]);

    float ax = 0.f, ay = 0.f, az = 0.f, aw = 0.f, z = 0.f;

    int i = beg;
    // 8-edge software pipeline: 16 front-batched LDG.64s (raw), convert lazily
    for (; i + 7 < end; i += 8) {
        int s[8];
#pragma unroll
        for (int j = 0; j < 8; j++) s[j] = __ldg(&g_esrc[i + j]);
        uint2 kraw[8], vraw[8];
#pragma unroll
        for (int j = 0; j < 8; j++)
            kraw[j] = *reinterpret_cast<const uint2*>(&g_Kh[(size_t)s[j] * OUT_DIM + lane * 4]);
#pragma unroll
        for (int j = 0; j < 8; j++)
            vraw[j] = *reinterpret_cast<const uint2*>(&g_Vh[(size_t)s[j] * OUT_DIM + lane * 4]);
#pragma unroll
        for (int j = 0; j < 8; j++) {
            F4 k = cvt_half4(kraw[j]);
            float sc = edge_score(k, qv);
            F4 v = cvt_half4(vraw[j]);
            ax = fmaf(sc, v.x, ax); ay = fmaf(sc, v.y, ay);
            az = fmaf(sc, v.z, az); aw = fmaf(sc, v.w, aw);
            z += sc;
        }
    }
    for (; i < end; i++) {
        int s0 = __ldg(&g_esrc[i]);
        F4 k0 = cvt_half4(*reinterpret_cast<const uint2*>(&g_Kh[(size_t)s0 * OUT_DIM + lane * 4]));
        F4 v0 = cvt_half4(*reinterpret_cast<const uint2*>(&g_Vh[(size_t)s0 * OUT_DIM + lane * 4]));
        float sc0 = edge_score(k0, qv);
        ax = fmaf(sc0, v0.x, ax); ay = fmaf(sc0, v0.y, ay);
        az = fmaf(sc0, v0.z, az); aw = fmaf(sc0, v0.w, aw);
        z += sc0;
    }

    const float inv = 1.0f / z;
    float4 o = make_float4(ax * inv, ay * inv, az * inv, aw * inv);
    *reinterpret_cast<float4*>(&out[(size_t)node * OUT_DIM + lane * 4]) = o;
}

// ---------------- launch ----------------
extern "C" void kernel_launch(void* const* d_in, const int* in_sizes, int n_in,
                              void* d_out, int out_size)
{
    const float* h   = (const float*)d_in[0];
    const int*   src = (const int*)  d_in[1];
    const int*   dst = (const int*)  d_in[2];
    const float* WQ  = (const float*)d_in[3];
    const float* WK  = (const float*)d_in[4];
    const float* WV  = (const float*)d_in[5];
    const float* bQ  = (const float*)d_in[6];
    const float* bK  = (const float*)d_in[7];
    const float* bV  = (const float*)d_in[8];
    float* out = (float*)d_out;

    (void)in_sizes; (void)n_in; (void)out_size;

    // CSR build (by destination)
    zero_cnt_kernel<<<(N_NODES + 255) / 256, 256>>>();
    hist_kernel<<<(E_EDGES / 4 + 255) / 256, 256>>>(dst);
    scan_kernel<<<1, 1024>>>();
    scatter_kernel<<<(E_EDGES / 4 + 255) / 256, 256>>>(src, dst);

    // fp16 tensor-core QKV projection
    dim3 ggrid((N_NODES + 127) / 128, 3);
    qkv_gemm_f16<<<ggrid, 256>>>(h, WQ, WK, WV, bQ, bK, bV);

    // warp-per-node gather + fused normalize (atomic-free)
    gather_kernel<<<(N_NODES * 32 + 255) / 256, 256>>>(out);
}

// round 7
// speedup vs baseline: 3.2016x; 1.1810x over previous
#include <cuda_runtime.h>
#include <cuda_fp16.h>

#define N_NODES 50000
#define E_EDGES 1600000
#define IN_DIM  128
#define OUT_DIM 128   // H*D = 8*16
#define H_HEADS 8

#define GEMM_BLOCKS_X ((N_NODES + 127) / 128)          // 391
#define GEMM_BLOCKS   (GEMM_BLOCKS_X * 3)              // 1173
#define HIST_BLOCKS   ((E_EDGES / 4 + 255) / 256)      // 1563

// ---------------- scratch (static device globals: allowed) ----------------
__device__ __align__(16) __half g_Qh[N_NODES * OUT_DIM];
__device__ __align__(16) __half g_Kh[N_NODES * OUT_DIM];
__device__ __align__(16) __half g_Vh[N_NODES * OUT_DIM];
__device__ int g_cnt[N_NODES];
__device__ int g_rowptr[N_NODES + 1];
__device__ int g_rank[E_EDGES];
__device__ int g_esrc[E_EDGES];

// ---------------- zero counts ----------------
__global__ void zero_cnt_kernel() {
    int i = blockIdx.x * blockDim.x + threadIdx.x;
    if (i < N_NODES) g_cnt[i] = 0;
}

// ---------------- tensor-core GEMM helpers ----------------
#define GK 64                 // k-half width
#define AS_LD 72              // (GK+8) halfs per A row
#define WS_LD 136             // (128+8) halfs per W row

__device__ __forceinline__ void ldsm_x4(unsigned& r0, unsigned& r1, unsigned& r2, unsigned& r3,
                                        const __half* p) {
    unsigned addr = (unsigned)__cvta_generic_to_shared(p);
    asm volatile("ldmatrix.sync.aligned.m8n8.x4.shared.b16 {%0,%1,%2,%3}, [%4];"
                 : "=r"(r0), "=r"(r1), "=r"(r2), "=r"(r3) : "r"(addr));
}
__device__ __forceinline__ void ldsm_x4_t(unsigned& r0, unsigned& r1, unsigned& r2, unsigned& r3,
                                          const __half* p) {
    unsigned addr = (unsigned)__cvta_generic_to_shared(p);
    asm volatile("ldmatrix.sync.aligned.m8n8.x4.trans.shared.b16 {%0,%1,%2,%3}, [%4];"
                 : "=r"(r0), "=r"(r1), "=r"(r2), "=r"(r3) : "r"(addr));
}
__device__ __forceinline__ void mma16816(float* c, const unsigned* a, const unsigned* b) {
    asm volatile(
        "mma.sync.aligned.m16n8k16.row.col.f32.f16.f16.f32 "
        "{%0,%1,%2,%3}, {%4,%5,%6,%7}, {%8,%9}, {%0,%1,%2,%3};"
        : "+f"(c[0]), "+f"(c[1]), "+f"(c[2]), "+f"(c[3])
        : "r"(a[0]), "r"(a[1]), "r"(a[2]), "r"(a[3]), "r"(b[0]), "r"(b[1]));
}

// ---------------- fused: QKV GEMM (blocks [0,GEMM_BLOCKS)) + hist (rest) ----
__global__ __launch_bounds__(256) void gemm_hist_kernel(
    const float* __restrict__ hin,
    const float* __restrict__ WQ, const float* __restrict__ WK, const float* __restrict__ WV,
    const float* __restrict__ bQ, const float* __restrict__ bK, const float* __restrict__ bV,
    const int* __restrict__ dst)
{
    __shared__ __half As[128 * AS_LD];
    __shared__ __half Ws[GK * WS_LD];

    const int t = threadIdx.x;

    if (blockIdx.x >= GEMM_BLOCKS) {
        // ---- histogram branch: 4 edges/thread, record rank ----
        int i = (blockIdx.x - GEMM_BLOCKS) * 256 + t;
        if (i < E_EDGES / 4) {
            int4 d = reinterpret_cast<const int4*>(dst)[i];
            int r0 = atomicAdd(&g_cnt[d.x], 1);
            int r1 = atomicAdd(&g_cnt[d.y], 1);
            int r2 = atomicAdd(&g_cnt[d.z], 1);
            int r3 = atomicAdd(&g_cnt[d.w], 1);
            reinterpret_cast<int4*>(g_rank)[i] = make_int4(r0, r1, r2, r3);
        }
        return;
    }

    // ---- GEMM branch ----
    const int bx = blockIdx.x % GEMM_BLOCKS_X;
    const int by = blockIdx.x / GEMM_BLOCKS_X;

    const float* W;
    const float* bias;
    __half* out;
    if (by == 0)      { W = WQ; bias = bQ; out = g_Qh; }
    else if (by == 1) { W = WK; bias = bK; out = g_Kh; }
    else              { W = WV; bias = bV; out = g_Vh; }

    const int lane   = t & 31;
    const int wid    = t >> 5;
    const int warp_m = wid >> 1;
    const int warp_n = wid & 1;
    const int row0   = bx * 128;

    float acc[2][8][4];
#pragma unroll
    for (int i = 0; i < 2; i++)
#pragma unroll
        for (int j = 0; j < 8; j++)
#pragma unroll
            for (int c = 0; c < 4; c++) acc[i][j][c] = 0.f;

    for (int kt = 0; kt < IN_DIM; kt += GK) {
#pragma unroll
        for (int i = 0; i < 8; i++) {
            int idx = t + i * 256;
            int r   = idx >> 4;
            int c4  = idx & 15;
            int row = row0 + r;
            float4 v = make_float4(0.f, 0.f, 0.f, 0.f);
            if (row < N_NODES)
                v = *reinterpret_cast<const float4*>(&hin[(size_t)row * IN_DIM + kt + c4 * 4]);
            __half2 h0 = __floats2half2_rn(v.x, v.y);
            __half2 h1 = __floats2half2_rn(v.z, v.w);
            *reinterpret_cast<__half2*>(&As[r * AS_LD + c4 * 4])     = h0;
            *reinterpret_cast<__half2*>(&As[r * AS_LD + c4 * 4 + 2]) = h1;
        }
#pragma unroll
        for (int i = 0; i < 8; i++) {
            int idx = t + i * 256;
            int k   = idx >> 5;
            int c4  = idx & 31;
            float4 v = *reinterpret_cast<const float4*>(&W[(size_t)(kt + k) * OUT_DIM + c4 * 4]);
            __half2 h0 = __floats2half2_rn(v.x, v.y);
            __half2 h1 = __floats2half2_rn(v.z, v.w);
            *reinterpret_cast<__half2*>(&Ws[k * WS_LD + c4 * 4])     = h0;
            *reinterpret_cast<__half2*>(&Ws[k * WS_LD + c4 * 4 + 2]) = h1;
        }
        __syncthreads();

#pragma unroll
        for (int kk = 0; kk < GK; kk += 16) {
            unsigned a[2][4];
#pragma unroll
            for (int i = 0; i < 2; i++) {
                int r = warp_m * 32 + i * 16 + (lane & 15);
                int c = kk + 8 * (lane >> 4);
                ldsm_x4(a[i][0], a[i][1], a[i][2], a[i][3], &As[r * AS_LD + c]);
            }
            unsigned b[4][4];
#pragma unroll
            for (int j = 0; j < 4; j++) {
                int kr = kk + (lane & 15);
                int c  = warp_n * 64 + j * 16 + 8 * (lane >> 4);
                ldsm_x4_t(b[j][0], b[j][1], b[j][2], b[j][3], &Ws[kr * WS_LD + c]);
            }
#pragma unroll
            for (int i = 0; i < 2; i++)
#pragma unroll
                for (int j2 = 0; j2 < 8; j2++)
                    mma16816(acc[i][j2], a[i], &b[j2 >> 1][(j2 & 1) * 2]);
        }
        __syncthreads();
    }

#pragma unroll
    for (int i = 0; i < 2; i++) {
        int row_a = row0 + warp_m * 32 + i * 16 + (lane >> 2);
        int row_b = row_a + 8;
#pragma unroll
        for (int j2 = 0; j2 < 8; j2++) {
            int col = warp_n * 64 + j2 * 8 + (lane & 3) * 2;
            float b0 = __ldg(&bias[col]);
            float b1 = __ldg(&bias[col + 1]);
            if (row_a < N_NODES) {
                __half2 o = __floats2half2_rn(acc[i][j2][0] + b0, acc[i][j2][1] + b1);
                *reinterpret_cast<__half2*>(&out[(size_t)row_a * OUT_DIM + col]) = o;
            }
            if (row_b < N_NODES) {
                __half2 o = __floats2half2_rn(acc[i][j2][2] + b0, acc[i][j2][3] + b1);
                *reinterpret_cast<__half2*>(&out[(size_t)row_b * OUT_DIM + col]) = o;
            }
        }
    }
}

// ---------------- scan (rowptr only; no cursors needed) ----------------
__global__ __launch_bounds__(1024) void scan_kernel() {
    __shared__ int sums[1024];
    const int CH = (N_NODES + 1023) / 1024;   // 49
    const int t = threadIdx.x;
    const int base = t * CH;
    int s = 0;
    for (int i = 0; i < CH; i++) {
        int idx = base + i;
        if (idx < N_NODES) s += g_cnt[idx];
    }
    sums[t] = s;
    __syncthreads();
    for (int off = 1; off < 1024; off <<= 1) {
        int v = (t >= off) ? sums[t - off] : 0;
        __syncthreads();
        sums[t] += v;
        __syncthreads();
    }
    int run = sums[t] - s;
    for (int i = 0; i < CH; i++) {
        int idx = base + i;
        if (idx < N_NODES) {
            g_rowptr[idx] = run;
            run += g_cnt[idx];
        }
    }
    if (t == 0) g_rowptr[N_NODES] = E_EDGES;
}

// ---------------- atomic-free scatter using precomputed ranks ----------------
__global__ void scatter_kernel(const int* __restrict__ src, const int* __restrict__ dst) {
    int i = blockIdx.x * blockDim.x + threadIdx.x;   // < E/4
    if (i < E_EDGES / 4) {
        int4 d = reinterpret_cast<const int4*>(dst)[i];
        int4 s = reinterpret_cast<const int4*>(src)[i];
        int4 r = reinterpret_cast<const int4*>(g_rank)[i];
        g_esrc[__ldg(&g_rowptr[d.x]) + r.x] = s.x;
        g_esrc[__ldg(&g_rowptr[d.y]) + r.y] = s.y;
        g_esrc[__ldg(&g_rowptr[d.z]) + r.z] = s.z;
        g_esrc[__ldg(&g_rowptr[d.w]) + r.w] = s.w;
    }
}

// ---------------- gather kernel: warp per dst node, fp16, 8-edge pipeline ----
struct F4 { float x, y, z, w; };

__device__ __forceinline__ F4 cvt_half4(uint2 raw) {
    __half2 h0 = *reinterpret_cast<__half2*>(&raw.x);
    __half2 h1 = *reinterpret_cast<__half2*>(&raw.y);
    float2 f0 = __half22float2(h0);
    float2 f1 = __half22float2(h1);
    F4 r; r.x = f0.x; r.y = f0.y; r.z = f1.x; r.w = f1.y;
    return r;
}

__device__ __forceinline__ float edge_score(const F4& kv, const F4& qv) {
    float p = kv.x * qv.x + kv.y * qv.y + kv.z * qv.z + kv.w * qv.w;
    p += __shfl_xor_sync(0xFFFFFFFFu, p, 1);
    p += __shfl_xor_sync(0xFFFFFFFFu, p, 2);
    return __expf(fminf(fmaxf(p * 0.25f, -5.f), 5.f));
}

__global__ __launch_bounds__(256) void gather_kernel(float* __restrict__ out) {
    const int node = (blockIdx.x * blockDim.x + threadIdx.x) >> 5;
    if (node >= N_NODES) return;
    const int lane = threadIdx.x & 31;

    const F4 qv = cvt_half4(*reinterpret_cast<const uint2*>(&g_Qh[(size_t)node * OUT_DIM + lane * 4]));
    const int beg = __ldg(&g_rowptr[node]);
    const int end = __ldg(&g_rowptr[node + 1]);

    float ax = 0.f, ay = 0.f, az = 0.f, aw = 0.f, z = 0.f;

    int i = beg;
    for (; i + 7 < end; i += 8) {
        int s[8];
#pragma unroll
        for (int j = 0; j < 8; j++) s[j] = __ldg(&g_esrc[i + j]);
        uint2 kraw[8], vraw[8];
#pragma unroll
        for (int j = 0; j < 8; j++)
            kraw[j] = *reinterpret_cast<const uint2*>(&g_Kh[(size_t)s[j] * OUT_DIM + lane * 4]);
#pragma unroll
        for (int j = 0; j < 8; j++)
            vraw[j] = *reinterpret_cast<const uint2*>(&g_Vh[(size_t)s[j] * OUT_DIM + lane * 4]);
#pragma unroll
        for (int j = 0; j < 8; j++) {
            F4 k = cvt_half4(kraw[j]);
            float sc = edge_score(k, qv);
            F4 v = cvt_half4(vraw[j]);
            ax = fmaf(sc, v.x, ax); ay = fmaf(sc, v.y, ay);
            az = fmaf(sc, v.z, az); aw = fmaf(sc, v.w, aw);
            z += sc;
        }
    }
    for (; i < end; i++) {
        int s0 = __ldg(&g_esrc[i]);
        F4 k0 = cvt_half4(*reinterpret_cast<const uint2*>(&g_Kh[(size_t)s0 * OUT_DIM + lane * 4]));
        F4 v0 = cvt_half4(*reinterpret_cast<const uint2*>(&g_Vh[(size_t)s0 * OUT_DIM + lane * 4]));
        float sc0 = edge_score(k0, qv);
        ax = fmaf(sc0, v0.x, ax); ay = fmaf(sc0, v0.y, ay);
        az = fmaf(sc0, v0.z, az); aw = fmaf(sc0, v0.w, aw);
        z += sc0;
    }

    const float inv = 1.0f / z;
    float4 o = make_float4(ax * inv, ay * inv, az * inv, aw * inv);
    *reinterpret_cast<float4*>(&out[(size_t)node * OUT_DIM + lane * 4]) = o;
}

// ---------------- launch ----------------
extern "C" void kernel_launch(void* const* d_in, const int* in_sizes, int n_in,
                              void* d_out, int out_size)
{
    const float* h   = (const float*)d_in[0];
    const int*   src = (const int*)  d_in[1];
    const int*   dst = (const int*)  d_in[2];
    const float* WQ  = (const float*)d_in[3];
    const float* WK  = (const float*)d_in[4];
    const float* WV  = (const float*)d_in[5];
    const float* bQ  = (const float*)d_in[6];
    const float* bK  = (const float*)d_in[7];
    const float* bV  = (const float*)d_in[8];
    float* out = (float*)d_out;

    (void)in_sizes; (void)n_in; (void)out_size;

    // 1) zero counts
    zero_cnt_kernel<<<(N_NODES + 255) / 256, 256>>>();

    // 2) fused QKV GEMM + histogram (independent work, one launch)
    gemm_hist_kernel<<<GEMM_BLOCKS + HIST_BLOCKS, 256>>>(h, WQ, WK, WV, bQ, bK, bV, dst);

    // 3) rowptr scan
    scan_kernel<<<1, 1024>>>();

    // 4) atomic-free scatter via ranks
    scatter_kernel<<<(E_EDGES / 4 + 255) / 256, 256>>>(src, dst);

    // 5) warp-per-node gather + fused normalize
    gather_kernel<<<(N_NODES * 32 + 255) / 256, 256>>>(out);
}

// round 10
// speedup vs baseline: 3.3423x; 1.0439x over previous
#include <cuda_runtime.h>
#include <cuda_fp16.h>

#define N_NODES 50000
#define E_EDGES 1600000
#define IN_DIM  128
#define OUT_DIM 128   // H*D = 8*16
#define H_HEADS 8

#define GEMM_BLOCKS_X ((N_NODES + 127) / 128)          // 391
#define GEMM_BLOCKS   (GEMM_BLOCKS_X * 3)              // 1173
#define HIST_BLOCKS   ((E_EDGES / 4 + 255) / 256)      // 1563

// ---------------- scratch (static device globals: allowed) ----------------
__device__ __align__(16) __half g_Qh[N_NODES * OUT_DIM];
// interleaved K/V: per node 256 halfs; chunk j (j=0..31): [k4j..k4j+3, v4j..v4j+3]
__device__ __align__(16) __half g_KVh[N_NODES * OUT_DIM * 2];
__device__ int g_cnt[N_NODES];
__device__ int g_rowptr[N_NODES + 1];
__device__ int g_rank[E_EDGES];
__device__ int g_esrc[E_EDGES];

// ---------------- zero counts ----------------
__global__ void zero_cnt_kernel() {
    int i = blockIdx.x * blockDim.x + threadIdx.x;
    if (i < N_NODES) g_cnt[i] = 0;
}

// ---------------- tensor-core GEMM helpers ----------------
#define GK 64                 // k-half width
#define AS_LD 72              // (GK+8) halfs per A row
#define WS_LD 136             // (128+8) halfs per W row

__device__ __forceinline__ void ldsm_x4(unsigned& r0, unsigned& r1, unsigned& r2, unsigned& r3,
                                        const __half* p) {
    unsigned addr = (unsigned)__cvta_generic_to_shared(p);
    asm volatile("ldmatrix.sync.aligned.m8n8.x4.shared.b16 {%0,%1,%2,%3}, [%4];"
                 : "=r"(r0), "=r"(r1), "=r"(r2), "=r"(r3) : "r"(addr));
}
__device__ __forceinline__ void ldsm_x4_t(unsigned& r0, unsigned& r1, unsigned& r2, unsigned& r3,
                                          const __half* p) {
    unsigned addr = (unsigned)__cvta_generic_to_shared(p);
    asm volatile("ldmatrix.sync.aligned.m8n8.x4.trans.shared.b16 {%0,%1,%2,%3}, [%4];"
                 : "=r"(r0), "=r"(r1), "=r"(r2), "=r"(r3) : "r"(addr));
}
__device__ __forceinline__ void mma16816(float* c, const unsigned* a, const unsigned* b) {
    asm volatile(
        "mma.sync.aligned.m16n8k16.row.col.f32.f16.f16.f32 "
        "{%0,%1,%2,%3}, {%4,%5,%6,%7}, {%8,%9}, {%0,%1,%2,%3};"
        : "+f"(c[0]), "+f"(c[1]), "+f"(c[2]), "+f"(c[3])
        : "r"(a[0]), "r"(a[1]), "r"(a[2]), "r"(a[3]), "r"(b[0]), "r"(b[1]));
}

// ---------------- fused: QKV GEMM (blocks [0,GEMM_BLOCKS)) + hist (rest) ----
__global__ __launch_bounds__(256) void gemm_hist_kernel(
    const float* __restrict__ hin,
    const float* __restrict__ WQ, const float* __restrict__ WK, const float* __restrict__ WV,
    const float* __restrict__ bQ, const float* __restrict__ bK, const float* __restrict__ bV,
    const int* __restrict__ dst)
{
    __shared__ __half As[128 * AS_LD];
    __shared__ __half Ws[GK * WS_LD];

    const int t = threadIdx.x;

    if (blockIdx.x >= GEMM_BLOCKS) {
        // ---- histogram branch: 4 edges/thread, record rank ----
        int i = (blockIdx.x - GEMM_BLOCKS) * 256 + t;
        if (i < E_EDGES / 4) {
            int4 d = reinterpret_cast<const int4*>(dst)[i];
            int r0 = atomicAdd(&g_cnt[d.x], 1);
            int r1 = atomicAdd(&g_cnt[d.y], 1);
            int r2 = atomicAdd(&g_cnt[d.z], 1);
            int r3 = atomicAdd(&g_cnt[d.w], 1);
            reinterpret_cast<int4*>(g_rank)[i] = make_int4(r0, r1, r2, r3);
        }
        return;
    }

    // ---- GEMM branch ----
    const int bx = blockIdx.x % GEMM_BLOCKS_X;
    const int by = blockIdx.x / GEMM_BLOCKS_X;

    const float* W;
    const float* bias;
    if (by == 0)      { W = WQ; bias = bQ; }
    else if (by == 1) { W = WK; bias = bK; }
    else              { W = WV; bias = bV; }

    const int lane   = t & 31;
    const int wid    = t >> 5;
    const int warp_m = wid >> 1;
    const int warp_n = wid & 1;
    const int row0   = bx * 128;

    float acc[2][8][4];
#pragma unroll
    for (int i = 0; i < 2; i++)
#pragma unroll
        for (int j = 0; j < 8; j++)
#pragma unroll
            for (int c = 0; c < 4; c++) acc[i][j][c] = 0.f;

    for (int kt = 0; kt < IN_DIM; kt += GK) {
#pragma unroll
        for (int i = 0; i < 8; i++) {
            int idx = t + i * 256;
            int r   = idx >> 4;
            int c4  = idx & 15;
            int row = row0 + r;
            float4 v = make_float4(0.f, 0.f, 0.f, 0.f);
            if (row < N_NODES)
                v = *reinterpret_cast<const float4*>(&hin[(size_t)row * IN_DIM + kt + c4 * 4]);
            __half2 h0 = __floats2half2_rn(v.x, v.y);
            __half2 h1 = __floats2half2_rn(v.z, v.w);
            *reinterpret_cast<__half2*>(&As[r * AS_LD + c4 * 4])     = h0;
            *reinterpret_cast<__half2*>(&As[r * AS_LD + c4 * 4 + 2]) = h1;
        }
#pragma unroll
        for (int i = 0; i < 8; i++) {
            int idx = t + i * 256;
            int k   = idx >> 5;
            int c4  = idx & 31;
            float4 v = *reinterpret_cast<const float4*>(&W[(size_t)(kt + k) * OUT_DIM + c4 * 4]);
            __half2 h0 = __floats2half2_rn(v.x, v.y);
            __half2 h1 = __floats2half2_rn(v.z, v.w);
            *reinterpret_cast<__half2*>(&Ws[k * WS_LD + c4 * 4])     = h0;
            *reinterpret_cast<__half2*>(&Ws[k * WS_LD + c4 * 4 + 2]) = h1;
        }
        __syncthreads();

#pragma unroll
        for (int kk = 0; kk < GK; kk += 16) {
            unsigned a[2][4];
#pragma unroll
            for (int i = 0; i < 2; i++) {
                int r = warp_m * 32 + i * 16 + (lane & 15);
                int c = kk + 8 * (lane >> 4);
                ldsm_x4(a[i][0], a[i][1], a[i][2], a[i][3], &As[r * AS_LD + c]);
            }
            unsigned b[4][4];
#pragma unroll
            for (int j = 0; j < 4; j++) {
                int kr = kk + (lane & 15);
                int c  = warp_n * 64 + j * 16 + 8 * (lane >> 4);
                ldsm_x4_t(b[j][0], b[j][1], b[j][2], b[j][3], &Ws[kr * WS_LD + c]);
            }
#pragma unroll
            for (int i = 0; i < 2; i++)
#pragma unroll
                for (int j2 = 0; j2 < 8; j2++)
                    mma16816(acc[i][j2], a[i], &b[j2 >> 1][(j2 & 1) * 2]);
        }
        __syncthreads();
    }

    // epilogue: +bias, fp16; Q -> g_Qh; K/V -> interleaved g_KVh
    const int kv_off = (by == 2) ? 4 : 0;
#pragma unroll
    for (int i = 0; i < 2; i++) {
        int row_a = row0 + warp_m * 32 + i * 16 + (lane >> 2);
        int row_b = row_a + 8;
#pragma unroll
        for (int j2 = 0; j2 < 8; j2++) {
            int col = warp_n * 64 + j2 * 8 + (lane & 3) * 2;
            float b0 = __ldg(&bias[col]);
            float b1 = __ldg(&bias[col + 1]);
            __half2 oa = __floats2half2_rn(acc[i][j2][0] + b0, acc[i][j2][1] + b1);
            __half2 ob = __floats2half2_rn(acc[i][j2][2] + b0, acc[i][j2][3] + b1);
            if (by == 0) {
                if (row_a < N_NODES)
                    *reinterpret_cast<__half2*>(&g_Qh[(size_t)row_a * OUT_DIM + col]) = oa;
                if (row_b < N_NODES)
                    *reinterpret_cast<__half2*>(&g_Qh[(size_t)row_b * OUT_DIM + col]) = ob;
            } else {
                // interleave remap: chunk = col>>2, within = col&3 (even), +4 for V
                size_t off = (size_t)(col >> 2) * 8 + kv_off + (col & 3);
                if (row_a < N_NODES)
                    *reinterpret_cast<__half2*>(&g_KVh[(size_t)row_a * OUT_DIM * 2 + off]) = oa;
                if (row_b < N_NODES)
                    *reinterpret_cast<__half2*>(&g_KVh[(size_t)row_b * OUT_DIM * 2 + off]) = ob;
            }
        }
    }
}

// ---------------- scan (rowptr only) ----------------
__global__ __launch_bounds__(1024) void scan_kernel() {
    __shared__ int sums[1024];
    const int CH = 52;                       // 1024*52 >= 50000, 52 % 4 == 0
    const int t = threadIdx.x;
    const int base = t * CH;
    int s = 0;
    for (int i = 0; i < CH; i += 4) {
        int idx = base + i;
        if (idx + 3 < N_NODES) {
            int4 c = *reinterpret_cast<const int4*>(&g_cnt[idx]);
            s += c.x + c.y + c.z + c.w;
        } else {
            for (int j = 0; j < 4; j++)
                if (idx + j < N_NODES) s += g_cnt[idx + j];
        }
    }
    sums[t] = s;
    __syncthreads();
    for (int off = 1; off < 1024; off <<= 1) {
        int v = (t >= off) ? sums[t - off] : 0;
        __syncthreads();
        sums[t] += v;
        __syncthreads();
    }
    int run = sums[t] - s;
    for (int i = 0; i < CH; i++) {
        int idx = base + i;
        if (idx < N_NODES) {
            g_rowptr[idx] = run;
            run += g_cnt[idx];
        }
    }
    if (t == 0) g_rowptr[N_NODES] = E_EDGES;
}

// ---------------- atomic-free scatter using precomputed ranks ----------------
__global__ void scatter_kernel(const int* __restrict__ src, const int* __restrict__ dst) {
    int i = blockIdx.x * blockDim.x + threadIdx.x;   // < E/4
    if (i < E_EDGES / 4) {
        int4 d = reinterpret_cast<const int4*>(dst)[i];
        int4 s = reinterpret_cast<const int4*>(src)[i];
        int4 r = reinterpret_cast<const int4*>(g_rank)[i];
        g_esrc[__ldg(&g_rowptr[d.x]) + r.x] = s.x;
        g_esrc[__ldg(&g_rowptr[d.y]) + r.y] = s.y;
        g_esrc[__ldg(&g_rowptr[d.z]) + r.z] = s.z;
        g_esrc[__ldg(&g_rowptr[d.w]) + r.w] = s.w;
    }
}

// ---------------- gather: warp per dst node, one LDG.128/edge/lane ----------
struct F4 { float x, y, z, w; };

__device__ __forceinline__ F4 cvt2(unsigned lo, unsigned hi) {
    __half2 h0 = *reinterpret_cast<__half2*>(&lo);
    __half2 h1 = *reinterpret_cast<__half2*>(&hi);
    float2 f0 = __half22float2(h0);
    float2 f1 = __half22float2(h1);
    F4 r; r.x = f0.x; r.y = f0.y; r.z = f1.x; r.w = f1.y;
    return r;
}

__device__ __forceinline__ float edge_score(const F4& kv, const F4& qv) {
    float p = kv.x * qv.x + kv.y * qv.y + kv.z * qv.z + kv.w * qv.w;
    p += __shfl_xor_sync(0xFFFFFFFFu, p, 1);
    p += __shfl_xor_sync(0xFFFFFFFFu, p, 2);
    return __expf(fminf(fmaxf(p * 0.25f, -5.f), 5.f));
}

__global__ __launch_bounds__(256) void gather_kernel(float* __restrict__ out) {
    const int node = (blockIdx.x * blockDim.x + threadIdx.x) >> 5;
    if (node >= N_NODES) return;
    const int lane = threadIdx.x & 31;

    const uint2 qraw = *reinterpret_cast<const uint2*>(&g_Qh[(size_t)node * OUT_DIM + lane * 4]);
    const F4 qv = cvt2(qraw.x, qraw.y);
    const int beg = __ldg(&g_rowptr[node]);
    const int end = __ldg(&g_rowptr[node + 1]);

    float ax = 0.f, ay = 0.f, az = 0.f, aw = 0.f, z = 0.f;

    int i = beg;
    for (; i + 7 < end; i += 8) {
        int s[8];
#pragma unroll
        for (int j = 0; j < 8; j++) s[j] = __ldg(&g_esrc[i + j]);
        uint4 kv[8];
#pragma unroll
        for (int j = 0; j < 8; j++)
            kv[j] = *reinterpret_cast<const uint4*>(&g_KVh[(size_t)s[j] * OUT_DIM * 2 + lane * 8]);
#pragma unroll
        for (int j = 0; j < 8; j++) {
            F4 k = cvt2(kv[j].x, kv[j].y);
            float sc = edge_score(k, qv);
            F4 v = cvt2(kv[j].z, kv[j].w);
            ax = fmaf(sc, v.x, ax); ay = fmaf(sc, v.y, ay);
            az = fmaf(sc, v.z, az); aw = fmaf(sc, v.w, aw);
            z += sc;
        }
    }
    for (; i < end; i++) {
        int s0 = __ldg(&g_esrc[i]);
        uint4 kv0 = *reinterpret_cast<const uint4*>(&g_KVh[(size_t)s0 * OUT_DIM * 2 + lane * 8]);
        F4 k0 = cvt2(kv0.x, kv0.y);
        F4 v0 = cvt2(kv0.z, kv0.w);
        float sc0 = edge_score(k0, qv);
        ax = fmaf(sc0, v0.x, ax); ay = fmaf(sc0, v0.y, ay);
        az = fmaf(sc0, v0.z, az); aw = fmaf(sc0, v0.w, aw);
        z += sc0;
    }

    const float inv = 1.0f / z;
    float4 o = make_float4(ax * inv, ay * inv, az * inv, aw * inv);
    *reinterpret_cast<float4*>(&out[(size_t)node * OUT_DIM + lane * 4]) = o;
}

// ---------------- launch ----------------
extern "C" void kernel_launch(void* const* d_in, const int* in_sizes, int n_in,
                              void* d_out, int out_size)
{
    const float* h   = (const float*)d_in[0];
    const int*   src = (const int*)  d_in[1];
    const int*   dst = (const int*)  d_in[2];
    const float* WQ  = (const float*)d_in[3];
    const float* WK  = (const float*)d_in[4];
    const float* WV  = (const float*)d_in[5];
    const float* bQ  = (const float*)d_in[6];
    const float* bK  = (const float*)d_in[7];
    const float* bV  = (const float*)d_in[8];
    float* out = (float*)d_out;

    (void)in_sizes; (void)n_in; (void)out_size;

    // 1) zero counts
    zero_cnt_kernel<<<(N_NODES + 255) / 256, 256>>>();

    // 2) fused QKV GEMM + histogram
    gemm_hist_kernel<<<GEMM_BLOCKS + HIST_BLOCKS, 256>>>(h, WQ, WK, WV, bQ, bK, bV, dst);

    // 3) rowptr scan
    scan_kernel<<<1, 1024>>>();

    // 4) atomic-free scatter via ranks
    scatter_kernel<<<(E_EDGES / 4 + 255) / 256, 256>>>(src, dst);

    // 5) warp-per-node gather + fused normalize
    gather_kernel<<<(N_NODES * 32 + 255) / 256, 256>>>(out);
}